// round 10
// baseline (speedup 1.0000x reference)
#include <cuda_runtime.h>
#include <cuda_bf16.h>

// Problem constants
#define BB   16
#define NN   1029
#define HH   16
#define HD   64
#define DD   1024
#define MM   (BB * NN)          // 16464
#define PREFIX 5                // N - NP
#define TOTAL  (MM * DD)        // 16859136

// Scratch (allocation-free rule: use __device__ globals)
__device__ float g_Q  [TOTAL];
__device__ float g_K  [TOTAL];
__device__ float g_V  [TOTAL];
__device__ float g_CTX[TOTAL];

__device__ __forceinline__ unsigned f2tf(float x) {
    unsigned r;
    asm("cvt.rna.tf32.f32 %0, %1;" : "=r"(r) : "f"(x));
    return r;
}

__device__ __forceinline__ void mma_tf32(
    float& c0, float& c1, float& c2, float& c3,
    unsigned a0, unsigned a1, unsigned a2, unsigned a3,
    unsigned b0, unsigned b1)
{
    asm volatile(
        "mma.sync.aligned.m16n8k8.row.col.f32.tf32.tf32.f32 "
        "{%0,%1,%2,%3}, {%4,%5,%6,%7}, {%8,%9}, {%0,%1,%2,%3};\n"
        : "+f"(c0), "+f"(c1), "+f"(c2), "+f"(c3)
        : "r"(a0), "r"(a1), "r"(a2), "r"(a3), "r"(b0), "r"(b1));
}

// ---------------------------------------------------------------------------
// TF32 tensor-core GEMM NT: C[m,n] = sum_k A[m,k] * W[n,k] + bias[n]
// MODE 0: plain row-major store to C [M, 1024]
// MODE 1: fused RoPE + transpose store to C as [B,H,N,HD]
// ---------------------------------------------------------------------------
#define KPAD 36
#define CPAD 132
#define GEMM_SMEM (128 * CPAD * 4)   // 67584 B >= 2*128*KPAD*4 = 36864 B

template <int MODE>
__global__ __launch_bounds__(256) void gemm_tf32(
    const float* __restrict__ A, const float* __restrict__ W,
    const float* __restrict__ bias, float* __restrict__ C, int M,
    const float* __restrict__ sinp, const float* __restrict__ cosp)
{
    extern __shared__ unsigned smem_dyn[];
    unsigned* As = smem_dyn;
    unsigned* Ws = As + 128 * KPAD;

    const int tid  = threadIdx.x;
    const int warp = tid >> 5;
    const int lane = tid & 31;
    const int g    = lane >> 2;   // 0..7
    const int q    = lane & 3;    // 0..3
    const int wm   = warp >> 2;   // 0..1
    const int wn   = warp & 3;    // 0..3
    const int row0 = blockIdx.y * 128;
    const int col0 = blockIdx.x * 128;

    float acc[4][4][4];
    #pragma unroll
    for (int mt = 0; mt < 4; mt++)
        #pragma unroll
        for (int nt = 0; nt < 4; nt++)
            #pragma unroll
            for (int i = 0; i < 4; i++) acc[mt][nt][i] = 0.f;

    int lrow[4], lk[4];
    #pragma unroll
    for (int j = 0; j < 4; j++) {
        int idx = tid + j * 256;
        lrow[j] = idx >> 3;
        lk[j]   = (idx & 7) * 4;
    }

    const float4 z4 = make_float4(0.f, 0.f, 0.f, 0.f);
    float4 pa[4], pw[4];
    #pragma unroll
    for (int j = 0; j < 4; j++) {
        int r = row0 + lrow[j];
        pa[j] = (r < M) ? *(const float4*)(A + (long long)r * DD + lk[j]) : z4;
        pw[j] = *(const float4*)(W + (long long)(col0 + lrow[j]) * DD + lk[j]);
    }

    for (int chunk = 0; chunk < DD / 32; chunk++) {
        #pragma unroll
        for (int j = 0; j < 4; j++) {
            unsigned* as = &As[lrow[j] * KPAD + lk[j]];
            as[0] = f2tf(pa[j].x); as[1] = f2tf(pa[j].y);
            as[2] = f2tf(pa[j].z); as[3] = f2tf(pa[j].w);
            unsigned* ws = &Ws[lrow[j] * KPAD + lk[j]];
            ws[0] = f2tf(pw[j].x); ws[1] = f2tf(pw[j].y);
            ws[2] = f2tf(pw[j].z); ws[3] = f2tf(pw[j].w);
        }
        __syncthreads();

        if (chunk + 1 < DD / 32) {
            int kb = (chunk + 1) * 32;
            #pragma unroll
            for (int j = 0; j < 4; j++) {
                int r = row0 + lrow[j];
                pa[j] = (r < M) ? *(const float4*)(A + (long long)r * DD + kb + lk[j]) : z4;
                pw[j] = *(const float4*)(W + (long long)(col0 + lrow[j]) * DD + kb + lk[j]);
            }
        }

        #pragma unroll
        for (int ks = 0; ks < 4; ks++) {
            const int kc = ks * 8 + q;
            unsigned af[4][4], bf[4][2];
            #pragma unroll
            for (int mt = 0; mt < 4; mt++) {
                int base = (wm * 64 + mt * 16 + g) * KPAD + kc;
                af[mt][0] = As[base];
                af[mt][1] = As[base + 8 * KPAD];
                af[mt][2] = As[base + 4];
                af[mt][3] = As[base + 8 * KPAD + 4];
            }
            #pragma unroll
            for (int nt = 0; nt < 4; nt++) {
                int base = (wn * 32 + nt * 8 + g) * KPAD + kc;
                bf[nt][0] = Ws[base];
                bf[nt][1] = Ws[base + 4];
            }
            #pragma unroll
            for (int mt = 0; mt < 4; mt++)
                #pragma unroll
                for (int nt = 0; nt < 4; nt++)
                    mma_tf32(acc[mt][nt][0], acc[mt][nt][1],
                             acc[mt][nt][2], acc[mt][nt][3],
                             af[mt][0], af[mt][1], af[mt][2], af[mt][3],
                             bf[nt][0], bf[nt][1]);
        }
        __syncthreads();
    }

    if (MODE == 0) {
        #pragma unroll
        for (int mt = 0; mt < 4; mt++) {
            int r0 = row0 + wm * 64 + mt * 16 + g;
            int r1 = r0 + 8;
            #pragma unroll
            for (int nt = 0; nt < 4; nt++) {
                int c = col0 + wn * 32 + nt * 8 + 2 * q;
                float bx = bias[c], by = bias[c + 1];
                if (r0 < M) {
                    float2 v = make_float2(acc[mt][nt][0] + bx, acc[mt][nt][1] + by);
                    *(float2*)(C + (long long)r0 * DD + c) = v;
                }
                if (r1 < M) {
                    float2 v = make_float2(acc[mt][nt][2] + bx, acc[mt][nt][3] + by);
                    *(float2*)(C + (long long)r1 * DD + c) = v;
                }
            }
        }
    } else {
        // fused epilogue: stage (bias applied), then RoPE + transpose store
        float* Cs = (float*)smem_dyn;   // 128 x CPAD
        #pragma unroll
        for (int mt = 0; mt < 4; mt++) {
            int lr0 = wm * 64 + mt * 16 + g;
            int lr1 = lr0 + 8;
            #pragma unroll
            for (int nt = 0; nt < 4; nt++) {
                int lc = wn * 32 + nt * 8 + 2 * q;
                float bx = bias[col0 + lc], by = bias[col0 + lc + 1];
                *(float2*)&Cs[lr0 * CPAD + lc] =
                    make_float2(acc[mt][nt][0] + bx, acc[mt][nt][1] + by);
                *(float2*)&Cs[lr1 * CPAD + lc] =
                    make_float2(acc[mt][nt][2] + bx, acc[mt][nt][3] + by);
            }
        }
        __syncthreads();

        #pragma unroll
        for (int i = 0; i < 16; i++) {
            int idx = tid + i * 256;
            int row = idx >> 5;             // 0..127
            int c4  = (idx & 31) * 4;       // 0..124
            int R = row0 + row;
            if (R >= M) continue;
            int b = R / NN;
            int t = R - b * NN;
            int gcol = col0 + c4;
            int h = gcol >> 6;
            int d = gcol & 63;

            float4 x = *(float4*)&Cs[row * CPAD + c4];
            float4 v = x;
            if (t >= PREFIX) {
                int pos = t - PREFIX;
                float4 cc = *(const float4*)(cosp + pos * HD + d);
                float4 ss = *(const float4*)(sinp + pos * HD + d);
                float4 xo = *(float4*)&Cs[row * CPAD + (c4 ^ 32)];
                if (d < 32) { xo.x = -xo.x; xo.y = -xo.y; xo.z = -xo.z; xo.w = -xo.w; }
                v.x = x.x * cc.x + xo.x * ss.x;
                v.y = x.y * cc.y + xo.y * ss.y;
                v.z = x.z * cc.z + xo.z * ss.z;
                v.w = x.w * cc.w + xo.w * ss.w;
            }
            *(float4*)(C + (((long long)(b * HH + h)) * NN + t) * HD + d) = v;
        }
    }
}

// ---------------------------------------------------------------------------
// Tensor-core flash attention, v2: 128-query x 128-kv tiles, LDS-optimized.
// Q,K: [B,H,N,HD].  V: [B,N,H*HD].  CTX: [B,N,H*HD].
// 256 threads (8 warps), 1 CTA/SM (174 KB smem).
// S phase: warp (qg 0..3, kg 0..1) -> S[qg*32..+31][kg*64..+63], 32x64 tile.
// Softmax: cross-warp (2 kv-groups) reduction via pmax/psum smem.
// PV: kv-split halves; warp (kg2, dg, hg) -> O^T[dg*32..+31][hg*64..+63]
//     over kv half kg2; two partial O's merged at the end.
// V stored transposed Vt[d][kv] stride 133 (conflict-free PV A-loads).
// ---------------------------------------------------------------------------
#define ST   68
#define PST  132
#define VST  133
#define OFF_QS   0
#define OFF_KS   8704               // 128*68
#define OFF_VT   17408              // +128*68
#define OFF_PS   25920              // +64*133 = 8512
#define OFF_PMAX 42816              // +128*132 = 16896
#define OFF_PSUM 43072
#define OFF_SCL  43328
#define OFF_LINV 43456
#define FA_SMEM  ((43456 + 128) * 4)   // 174336 B

__global__ __launch_bounds__(256, 1) void flash_attn_tc(
    const float* __restrict__ Q, const float* __restrict__ K,
    const float* __restrict__ Vy, float* __restrict__ CTX)
{
    extern __shared__ unsigned sm_u[];
    unsigned* Qs = sm_u + OFF_QS;           // 128 x ST  (q x d)
    unsigned* Ks = sm_u + OFF_KS;           // 128 x ST  (kv x d)
    unsigned* Vt = sm_u + OFF_VT;           // 64 x VST  (d x kv)
    unsigned* Ps = sm_u + OFF_PS;           // 128 x PST (q x kv) / O stage
    float* pmax = (float*)(sm_u + OFF_PMAX);  // [2][128]
    float* psum = (float*)(sm_u + OFF_PSUM);  // [2][128]
    float* scl  = (float*)(sm_u + OFF_SCL);   // [128]
    float* linv = (float*)(sm_u + OFF_LINV);  // [128]

    const int q0 = blockIdx.x * 128;
    const int h  = blockIdx.y;
    const int b  = blockIdx.z;
    const long long baseQ = ((long long)(b * HH + h)) * NN * HD;
    const int tid  = threadIdx.x;
    const int warp = tid >> 5;
    const int lane = tid & 31;
    const int g    = lane >> 2;
    const int q    = lane & 3;
    // S-phase roles
    const int qg    = warp & 3;
    const int kg    = warp >> 2;
    const int qbase = qg * 32;
    const int kvb   = kg * 64;
    // PV roles
    const int kg2   = warp >> 2;
    const int dbase = ((warp >> 1) & 1) * 32;
    const int qpb   = (warp & 1) * 64;

    // load Q tile (scaled by HD^-0.5)
    #pragma unroll
    for (int i = 0; i < 8; i++) {
        int idx = tid + i * 256;
        int row = idx >> 4, c4 = (idx & 15) * 4;
        int r = q0 + row;
        float4 v = (r < NN) ? *(const float4*)(Q + baseQ + (long long)r * HD + c4)
                            : make_float4(0.f, 0.f, 0.f, 0.f);
        unsigned* p = &Qs[row * ST + c4];
        p[0] = f2tf(v.x * 0.125f); p[1] = f2tf(v.y * 0.125f);
        p[2] = f2tf(v.z * 0.125f); p[3] = f2tf(v.w * 0.125f);
    }

    float m[2][2], l[2][2];
    #pragma unroll
    for (int mt = 0; mt < 2; mt++) {
        m[mt][0] = -1e30f; m[mt][1] = -1e30f;
        l[mt][0] = 0.f;    l[mt][1] = 0.f;
    }
    float oacc[2][8][4];
    #pragma unroll
    for (int mt = 0; mt < 2; mt++)
        #pragma unroll
        for (int nt = 0; nt < 8; nt++)
            #pragma unroll
            for (int i = 0; i < 4; i++) oacc[mt][nt][i] = 0.f;

    for (int k0 = 0; k0 < NN; k0 += 128) {
        __syncthreads();   // prev PV done before overwriting K/V tiles
        // load K tile [kv][d] and V tile transposed Vt[d][kv]
        #pragma unroll
        for (int i = 0; i < 8; i++) {
            int idx = tid + i * 256;
            int j = idx >> 4, c4 = (idx & 15) * 4;
            int kv = k0 + j;
            float4 kvec, vvec;
            if (kv < NN) {
                kvec = *(const float4*)(K + baseQ + (long long)kv * HD + c4);
                vvec = *(const float4*)(Vy + ((long long)(b * NN + kv)) * DD + h * HD + c4);
            } else {
                kvec = make_float4(0.f, 0.f, 0.f, 0.f);
                vvec = kvec;
            }
            unsigned* pk = &Ks[j * ST + c4];
            pk[0] = f2tf(kvec.x); pk[1] = f2tf(kvec.y);
            pk[2] = f2tf(kvec.z); pk[3] = f2tf(kvec.w);
            Vt[(c4 + 0) * VST + j] = f2tf(vvec.x);
            Vt[(c4 + 1) * VST + j] = f2tf(vvec.y);
            Vt[(c4 + 2) * VST + j] = f2tf(vvec.z);
            Vt[(c4 + 3) * VST + j] = f2tf(vvec.w);
        }
        __syncthreads();

        // ---- S = Q @ K^T : warp tile 32q x 64kv ----
        float sacc[2][8][4];
        #pragma unroll
        for (int mt = 0; mt < 2; mt++)
            #pragma unroll
            for (int nt = 0; nt < 8; nt++)
                #pragma unroll
                for (int i = 0; i < 4; i++) sacc[mt][nt][i] = 0.f;

        #pragma unroll
        for (int ks = 0; ks < 8; ks++) {
            const int kc = ks * 8 + q;
            unsigned a[2][4];
            #pragma unroll
            for (int mt = 0; mt < 2; mt++) {
                int r = (qbase + mt * 16 + g) * ST + kc;
                a[mt][0] = Qs[r];
                a[mt][1] = Qs[r + 8 * ST];
                a[mt][2] = Qs[r + 4];
                a[mt][3] = Qs[r + 8 * ST + 4];
            }
            #pragma unroll
            for (int nt = 0; nt < 8; nt++) {
                int kr = (kvb + nt * 8 + g) * ST + kc;
                unsigned b0 = Ks[kr], b1 = Ks[kr + 4];
                #pragma unroll
                for (int mt = 0; mt < 2; mt++)
                    mma_tf32(sacc[mt][nt][0], sacc[mt][nt][1],
                             sacc[mt][nt][2], sacc[mt][nt][3],
                             a[mt][0], a[mt][1], a[mt][2], a[mt][3], b0, b1);
            }
        }

        // mask out-of-range kv columns
        if (k0 + 128 > NN) {
            #pragma unroll
            for (int nt = 0; nt < 8; nt++) {
                int c = k0 + kvb + nt * 8 + 2 * q;
                if (c >= NN) {
                    sacc[0][nt][0] = -1e30f; sacc[0][nt][2] = -1e30f;
                    sacc[1][nt][0] = -1e30f; sacc[1][nt][2] = -1e30f;
                }
                if (c + 1 >= NN) {
                    sacc[0][nt][1] = -1e30f; sacc[0][nt][3] = -1e30f;
                    sacc[1][nt][1] = -1e30f; sacc[1][nt][3] = -1e30f;
                }
            }
        }

        // ---- partial row max over this warp's 64 kv ----
        float tm[2][2];
        #pragma unroll
        for (int mt = 0; mt < 2; mt++) {
            float t0 = -1e30f, t1 = -1e30f;
            #pragma unroll
            for (int nt = 0; nt < 8; nt++) {
                t0 = fmaxf(t0, fmaxf(sacc[mt][nt][0], sacc[mt][nt][1]));
                t1 = fmaxf(t1, fmaxf(sacc[mt][nt][2], sacc[mt][nt][3]));
            }
            t0 = fmaxf(t0, __shfl_xor_sync(0xffffffffu, t0, 1));
            t0 = fmaxf(t0, __shfl_xor_sync(0xffffffffu, t0, 2));
            t1 = fmaxf(t1, __shfl_xor_sync(0xffffffffu, t1, 1));
            t1 = fmaxf(t1, __shfl_xor_sync(0xffffffffu, t1, 2));
            tm[mt][0] = t0; tm[mt][1] = t1;
        }
        if (q == 0) {
            #pragma unroll
            for (int mt = 0; mt < 2; mt++) {
                pmax[kg * 128 + qbase + mt * 16 + g]     = tm[mt][0];
                pmax[kg * 128 + qbase + mt * 16 + g + 8] = tm[mt][1];
            }
        }
        __syncthreads();

        // combined max, rescale factors
        float sc[2][2];
        #pragma unroll
        for (int mt = 0; mt < 2; mt++)
            #pragma unroll
            for (int hh = 0; hh < 2; hh++) {
                int r = qbase + mt * 16 + g + hh * 8;
                float cmb = fmaxf(pmax[r], pmax[128 + r]);
                float mn = fmaxf(m[mt][hh], cmb);
                sc[mt][hh] = __expf(m[mt][hh] - mn);
                m[mt][hh] = mn;
            }

        // p = exp(s - m), partial sums, store P (tf32)
        float ps_[2][2] = {{0.f, 0.f}, {0.f, 0.f}};
        #pragma unroll
        for (int mt = 0; mt < 2; mt++) {
            int rlo = qbase + mt * 16 + g;
            #pragma unroll
            for (int nt = 0; nt < 8; nt++) {
                float p0 = __expf(sacc[mt][nt][0] - m[mt][0]);
                float p1 = __expf(sacc[mt][nt][1] - m[mt][0]);
                float p2 = __expf(sacc[mt][nt][2] - m[mt][1]);
                float p3 = __expf(sacc[mt][nt][3] - m[mt][1]);
                ps_[mt][0] += p0 + p1;
                ps_[mt][1] += p2 + p3;
                *(uint2*)&Ps[rlo * PST + kvb + nt * 8 + 2 * q] =
                    make_uint2(f2tf(p0), f2tf(p1));
                *(uint2*)&Ps[(rlo + 8) * PST + kvb + nt * 8 + 2 * q] =
                    make_uint2(f2tf(p2), f2tf(p3));
            }
        }
        #pragma unroll
        for (int mt = 0; mt < 2; mt++)
            #pragma unroll
            for (int hh = 0; hh < 2; hh++) {
                ps_[mt][hh] += __shfl_xor_sync(0xffffffffu, ps_[mt][hh], 1);
                ps_[mt][hh] += __shfl_xor_sync(0xffffffffu, ps_[mt][hh], 2);
            }
        if (q == 0) {
            #pragma unroll
            for (int mt = 0; mt < 2; mt++) {
                int rlo = qbase + mt * 16 + g;
                psum[kg * 128 + rlo]     = ps_[mt][0];
                psum[kg * 128 + rlo + 8] = ps_[mt][1];
                if (kg == 0) {
                    scl[rlo]     = sc[mt][0];
                    scl[rlo + 8] = sc[mt][1];
                }
            }
        }
        __syncthreads();   // psum + Ps + scl visible

        // l update
        #pragma unroll
        for (int mt = 0; mt < 2; mt++)
            #pragma unroll
            for (int hh = 0; hh < 2; hh++) {
                int r = qbase + mt * 16 + g + hh * 8;
                l[mt][hh] = l[mt][hh] * sc[mt][hh] + psum[r] + psum[128 + r];
            }

        // ---- PV: O^T(partial, kv-half kg2) += V^T @ P^T ----
        #pragma unroll
        for (int nt = 0; nt < 8; nt++) {
            float s0 = scl[qpb + nt * 8 + 2 * q];
            float s1 = scl[qpb + nt * 8 + 2 * q + 1];
            #pragma unroll
            for (int mt = 0; mt < 2; mt++) {
                oacc[mt][nt][0] *= s0; oacc[mt][nt][1] *= s1;
                oacc[mt][nt][2] *= s0; oacc[mt][nt][3] *= s1;
            }
        }
        #pragma unroll
        for (int ks = 0; ks < 8; ks++) {
            const int kvi = kg2 * 64 + ks * 8 + q;
            unsigned a[2][4];
            #pragma unroll
            for (int mt = 0; mt < 2; mt++) {
                int dcol = dbase + mt * 16 + g;
                a[mt][0] = Vt[dcol * VST + kvi];
                a[mt][1] = Vt[(dcol + 8) * VST + kvi];
                a[mt][2] = Vt[dcol * VST + kvi + 4];
                a[mt][3] = Vt[(dcol + 8) * VST + kvi + 4];
            }
            #pragma unroll
            for (int nt = 0; nt < 8; nt++) {
                int qr = (qpb + nt * 8 + g) * PST + kvi;
                unsigned b0 = Ps[qr], b1 = Ps[qr + 4];
                #pragma unroll
                for (int mt = 0; mt < 2; mt++)
                    mma_tf32(oacc[mt][nt][0], oacc[mt][nt][1],
                             oacc[mt][nt][2], oacc[mt][nt][3],
                             a[mt][0], a[mt][1], a[mt][2], a[mt][3], b0, b1);
            }
        }
    }

    // final 1/l (written by kg==0 S-warps, covering all 128 rows)
    if (kg == 0 && q == 0) {
        #pragma unroll
        for (int mt = 0; mt < 2; mt++) {
            int rlo = qbase + mt * 16 + g;
            linv[rlo]     = 1.f / l[mt][0];
            linv[rlo + 8] = 1.f / l[mt][1];
        }
    }
    __syncthreads();

    // merge the two kv-half partial O's into Osm (reuse Ps as float)
    float* Osm = (float*)Ps;    // [q][d] stride PST, cols 0..63
    if (kg2 == 0) {
        #pragma unroll
        for (int mt = 0; mt < 2; mt++) {
            int d = dbase + mt * 16 + g;
            #pragma unroll
            for (int nt = 0; nt < 8; nt++) {
                int qc = qpb + nt * 8 + 2 * q;
                float i0 = linv[qc], i1 = linv[qc + 1];
                Osm[qc * PST + d]           = oacc[mt][nt][0] * i0;
                Osm[(qc + 1) * PST + d]     = oacc[mt][nt][1] * i1;
                Osm[qc * PST + d + 8]       = oacc[mt][nt][2] * i0;
                Osm[(qc + 1) * PST + d + 8] = oacc[mt][nt][3] * i1;
            }
        }
    }
    __syncthreads();
    if (kg2 == 1) {
        #pragma unroll
        for (int mt = 0; mt < 2; mt++) {
            int d = dbase + mt * 16 + g;
            #pragma unroll
            for (int nt = 0; nt < 8; nt++) {
                int qc = qpb + nt * 8 + 2 * q;
                float i0 = linv[qc], i1 = linv[qc + 1];
                Osm[qc * PST + d]           += oacc[mt][nt][0] * i0;
                Osm[(qc + 1) * PST + d]     += oacc[mt][nt][1] * i1;
                Osm[qc * PST + d + 8]       += oacc[mt][nt][2] * i0;
                Osm[(qc + 1) * PST + d + 8] += oacc[mt][nt][3] * i1;
            }
        }
    }
    __syncthreads();

    // coalesced output
    #pragma unroll
    for (int i = 0; i < 8; i++) {
        int idx = tid + i * 256;
        int row = idx >> 4, c4 = (idx & 15) * 4;
        int r = q0 + row;
        if (r < NN) {
            float4 v = *(float4*)&Osm[row * PST + c4];
            *(float4*)(CTX + ((long long)(b * NN + r)) * DD + h * HD + c4) = v;
        }
    }
}

// ---------------------------------------------------------------------------
extern "C" void kernel_launch(void* const* d_in, const int* in_sizes, int n_in,
                              void* d_out, int out_size)
{
    const float* X    = (const float*)d_in[0];
    const float* sinp = (const float*)d_in[1];
    const float* cosp = (const float*)d_in[2];
    const float* Wq   = (const float*)d_in[3];
    const float* bq   = (const float*)d_in[4];
    const float* Wk   = (const float*)d_in[5];
    const float* bk   = (const float*)d_in[6];
    const float* Wv   = (const float*)d_in[7];
    const float* bv   = (const float*)d_in[8];
    const float* Wo   = (const float*)d_in[9];
    const float* bo   = (const float*)d_in[10];
    float* OUT = (float*)d_out;

    float *Qb, *Kb, *Vb, *CTX;
    cudaGetSymbolAddress((void**)&Qb,  g_Q);
    cudaGetSymbolAddress((void**)&Kb,  g_K);
    cudaGetSymbolAddress((void**)&Vb,  g_V);
    cudaGetSymbolAddress((void**)&CTX, g_CTX);

    cudaFuncSetAttribute(gemm_tf32<0>,
                         cudaFuncAttributeMaxDynamicSharedMemorySize, GEMM_SMEM);
    cudaFuncSetAttribute(gemm_tf32<1>,
                         cudaFuncAttributeMaxDynamicSharedMemorySize, GEMM_SMEM);
    cudaFuncSetAttribute(flash_attn_tc,
                         cudaFuncAttributeMaxDynamicSharedMemorySize, FA_SMEM);

    dim3 ggrid(DD / 128, (MM + 127) / 128);
    dim3 gblk(256);

    // Q/K projections with fused RoPE+transpose -> [B,H,N,HD]
    gemm_tf32<1><<<ggrid, gblk, GEMM_SMEM>>>(X, Wq, bq, Qb, MM, sinp, cosp);
    gemm_tf32<1><<<ggrid, gblk, GEMM_SMEM>>>(X, Wk, bk, Kb, MM, sinp, cosp);
    // V projection (stays in [B,N,H*HD]; attention reads it directly)
    gemm_tf32<0><<<ggrid, gblk, GEMM_SMEM>>>(X, Wv, bv, Vb, MM, sinp, cosp);

    // tensor-core attention
    dim3 agrid((NN + 127) / 128, HH, BB);   // (9,16,16)
    flash_attn_tc<<<agrid, 256, FA_SMEM>>>(Qb, Kb, Vb, CTX);

    // output projection straight into d_out
    gemm_tf32<0><<<ggrid, gblk, GEMM_SMEM>>>(CTX, Wo, bo, OUT, MM, sinp, cosp);
}

// round 11
// speedup vs baseline: 1.2517x; 1.2517x over previous
#include <cuda_runtime.h>
#include <cuda_fp16.h>
#include <cuda_bf16.h>

// Problem constants
#define BB   16
#define NN   1029
#define HH   16
#define HD   64
#define DD   1024
#define MM   (BB * NN)          // 16464
#define PREFIX 5                // N - NP
#define TOTAL  (MM * DD)        // 16859136

// Scratch (allocation-free rule: use __device__ globals)
__device__ float g_Q  [TOTAL];
__device__ float g_K  [TOTAL];
__device__ float g_V  [TOTAL];
__device__ float g_CTX[TOTAL];

__device__ __forceinline__ unsigned f2tf(float x) {
    unsigned r;
    asm("cvt.rna.tf32.f32 %0, %1;" : "=r"(r) : "f"(x));
    return r;
}

__device__ __forceinline__ void mma_tf32(
    float& c0, float& c1, float& c2, float& c3,
    unsigned a0, unsigned a1, unsigned a2, unsigned a3,
    unsigned b0, unsigned b1)
{
    asm volatile(
        "mma.sync.aligned.m16n8k8.row.col.f32.tf32.tf32.f32 "
        "{%0,%1,%2,%3}, {%4,%5,%6,%7}, {%8,%9}, {%0,%1,%2,%3};\n"
        : "+f"(c0), "+f"(c1), "+f"(c2), "+f"(c3)
        : "r"(a0), "r"(a1), "r"(a2), "r"(a3), "r"(b0), "r"(b1));
}

__device__ __forceinline__ void mma_f16(
    float& c0, float& c1, float& c2, float& c3,
    unsigned a0, unsigned a1, unsigned a2, unsigned a3,
    unsigned b0, unsigned b1)
{
    asm volatile(
        "mma.sync.aligned.m16n8k16.row.col.f32.f16.f16.f32 "
        "{%0,%1,%2,%3}, {%4,%5,%6,%7}, {%8,%9}, {%0,%1,%2,%3};\n"
        : "+f"(c0), "+f"(c1), "+f"(c2), "+f"(c3)
        : "r"(a0), "r"(a1), "r"(a2), "r"(a3), "r"(b0), "r"(b1));
}

// ---------------------------------------------------------------------------
// TF32 tensor-core GEMM NT: C[m,n] = sum_k A[m,k] * W[n,k] + bias[n]
// MODE 0: plain row-major store to C [M, 1024]
// MODE 1: fused RoPE + transpose store to C as [B,H,N,HD]
// ---------------------------------------------------------------------------
#define KPAD 36
#define CPAD 132
#define GEMM_SMEM (128 * CPAD * 4)

template <int MODE>
__global__ __launch_bounds__(256) void gemm_tf32(
    const float* __restrict__ A, const float* __restrict__ W,
    const float* __restrict__ bias, float* __restrict__ C, int M,
    const float* __restrict__ sinp, const float* __restrict__ cosp)
{
    extern __shared__ unsigned smem_dyn[];
    unsigned* As = smem_dyn;
    unsigned* Ws = As + 128 * KPAD;

    const int tid  = threadIdx.x;
    const int warp = tid >> 5;
    const int lane = tid & 31;
    const int g    = lane >> 2;
    const int q    = lane & 3;
    const int wm   = warp >> 2;
    const int wn   = warp & 3;
    const int row0 = blockIdx.y * 128;
    const int col0 = blockIdx.x * 128;

    float acc[4][4][4];
    #pragma unroll
    for (int mt = 0; mt < 4; mt++)
        #pragma unroll
        for (int nt = 0; nt < 4; nt++)
            #pragma unroll
            for (int i = 0; i < 4; i++) acc[mt][nt][i] = 0.f;

    int lrow[4], lk[4];
    #pragma unroll
    for (int j = 0; j < 4; j++) {
        int idx = tid + j * 256;
        lrow[j] = idx >> 3;
        lk[j]   = (idx & 7) * 4;
    }

    const float4 z4 = make_float4(0.f, 0.f, 0.f, 0.f);
    float4 pa[4], pw[4];
    #pragma unroll
    for (int j = 0; j < 4; j++) {
        int r = row0 + lrow[j];
        pa[j] = (r < M) ? *(const float4*)(A + (long long)r * DD + lk[j]) : z4;
        pw[j] = *(const float4*)(W + (long long)(col0 + lrow[j]) * DD + lk[j]);
    }

    for (int chunk = 0; chunk < DD / 32; chunk++) {
        #pragma unroll
        for (int j = 0; j < 4; j++) {
            unsigned* as = &As[lrow[j] * KPAD + lk[j]];
            as[0] = f2tf(pa[j].x); as[1] = f2tf(pa[j].y);
            as[2] = f2tf(pa[j].z); as[3] = f2tf(pa[j].w);
            unsigned* ws = &Ws[lrow[j] * KPAD + lk[j]];
            ws[0] = f2tf(pw[j].x); ws[1] = f2tf(pw[j].y);
            ws[2] = f2tf(pw[j].z); ws[3] = f2tf(pw[j].w);
        }
        __syncthreads();

        if (chunk + 1 < DD / 32) {
            int kb = (chunk + 1) * 32;
            #pragma unroll
            for (int j = 0; j < 4; j++) {
                int r = row0 + lrow[j];
                pa[j] = (r < M) ? *(const float4*)(A + (long long)r * DD + kb + lk[j]) : z4;
                pw[j] = *(const float4*)(W + (long long)(col0 + lrow[j]) * DD + kb + lk[j]);
            }
        }

        #pragma unroll
        for (int ks = 0; ks < 4; ks++) {
            const int kc = ks * 8 + q;
            unsigned af[4][4], bf[4][2];
            #pragma unroll
            for (int mt = 0; mt < 4; mt++) {
                int base = (wm * 64 + mt * 16 + g) * KPAD + kc;
                af[mt][0] = As[base];
                af[mt][1] = As[base + 8 * KPAD];
                af[mt][2] = As[base + 4];
                af[mt][3] = As[base + 8 * KPAD + 4];
            }
            #pragma unroll
            for (int nt = 0; nt < 4; nt++) {
                int base = (wn * 32 + nt * 8 + g) * KPAD + kc;
                bf[nt][0] = Ws[base];
                bf[nt][1] = Ws[base + 4];
            }
            #pragma unroll
            for (int mt = 0; mt < 4; mt++)
                #pragma unroll
                for (int nt = 0; nt < 4; nt++)
                    mma_tf32(acc[mt][nt][0], acc[mt][nt][1],
                             acc[mt][nt][2], acc[mt][nt][3],
                             af[mt][0], af[mt][1], af[mt][2], af[mt][3],
                             bf[nt][0], bf[nt][1]);
        }
        __syncthreads();
    }

    if (MODE == 0) {
        #pragma unroll
        for (int mt = 0; mt < 4; mt++) {
            int r0 = row0 + wm * 64 + mt * 16 + g;
            int r1 = r0 + 8;
            #pragma unroll
            for (int nt = 0; nt < 4; nt++) {
                int c = col0 + wn * 32 + nt * 8 + 2 * q;
                float bx = bias[c], by = bias[c + 1];
                if (r0 < M) {
                    float2 v = make_float2(acc[mt][nt][0] + bx, acc[mt][nt][1] + by);
                    *(float2*)(C + (long long)r0 * DD + c) = v;
                }
                if (r1 < M) {
                    float2 v = make_float2(acc[mt][nt][2] + bx, acc[mt][nt][3] + by);
                    *(float2*)(C + (long long)r1 * DD + c) = v;
                }
            }
        }
    } else {
        float* Cs = (float*)smem_dyn;   // 128 x CPAD
        #pragma unroll
        for (int mt = 0; mt < 4; mt++) {
            int lr0 = wm * 64 + mt * 16 + g;
            int lr1 = lr0 + 8;
            #pragma unroll
            for (int nt = 0; nt < 4; nt++) {
                int lc = wn * 32 + nt * 8 + 2 * q;
                float bx = bias[col0 + lc], by = bias[col0 + lc + 1];
                *(float2*)&Cs[lr0 * CPAD + lc] =
                    make_float2(acc[mt][nt][0] + bx, acc[mt][nt][1] + by);
                *(float2*)&Cs[lr1 * CPAD + lc] =
                    make_float2(acc[mt][nt][2] + bx, acc[mt][nt][3] + by);
            }
        }
        __syncthreads();

        #pragma unroll
        for (int i = 0; i < 16; i++) {
            int idx = tid + i * 256;
            int row = idx >> 5;
            int c4  = (idx & 31) * 4;
            int R = row0 + row;
            if (R >= M) continue;
            int b = R / NN;
            int t = R - b * NN;
            int gcol = col0 + c4;
            int h = gcol >> 6;
            int d = gcol & 63;

            float4 x = *(float4*)&Cs[row * CPAD + c4];
            float4 v = x;
            if (t >= PREFIX) {
                int pos = t - PREFIX;
                float4 cc = *(const float4*)(cosp + pos * HD + d);
                float4 ss = *(const float4*)(sinp + pos * HD + d);
                float4 xo = *(float4*)&Cs[row * CPAD + (c4 ^ 32)];
                if (d < 32) { xo.x = -xo.x; xo.y = -xo.y; xo.z = -xo.z; xo.w = -xo.w; }
                v.x = x.x * cc.x + xo.x * ss.x;
                v.y = x.y * cc.y + xo.y * ss.y;
                v.z = x.z * cc.z + xo.z * ss.z;
                v.w = x.w * cc.w + xo.w * ss.w;
            }
            *(float4*)(C + (((long long)(b * HH + h)) * NN + t) * HD + d) = v;
        }
    }
}

// ---------------------------------------------------------------------------
// FP16 tensor-core flash attention (R9 structure, half the LDS traffic).
// Q,K: [B,H,N,HD].  V: [B,N,H*HD].  CTX: [B,N,H*HD].
// 256 threads (8 warps), 128-query tile, 64-kv tiles, 2 CTAs/SM.
// S: warp w -> q rows w*16..+15 x 64 kv (mma m16n8k16.f16).
// PV: O^T, warp -> d rows (w&3)*16..+15 x q cols (w>>2)*64..+63;
//     A-frag (V^T) via ldmatrix.x4.trans.b16 from row-major V tile.
// All smem tiles half, stride 72 (conflict-free: 72h = 36w, 36%32=4).
// ---------------------------------------------------------------------------
#define HST 72
#define OST 68
#define FA_SMEM (27648 * 2 + 256 * 4)   // 56320 B

__global__ __launch_bounds__(256, 2) void flash_attn_tc(
    const float* __restrict__ Q, const float* __restrict__ K,
    const float* __restrict__ Vy, float* __restrict__ CTX)
{
    extern __shared__ __half sm_h[];
    __half* Qs = sm_h;                  // 128 x HST
    __half* Ks = Qs + 128 * HST;        // 64 x HST  (kv x d)
    __half* Vs = Ks + 64 * HST;         // 64 x HST  (kv x d)
    __half* Ps = Vs + 64 * HST;         // 128 x HST (q x kv)
    float* scl  = (float*)(sm_h + 27648);   // 128
    float* linv = scl + 128;                // 128

    const int q0 = blockIdx.x * 128;
    const int h  = blockIdx.y;
    const int b  = blockIdx.z;
    const long long baseQ = ((long long)(b * HH + h)) * NN * HD;
    const int tid  = threadIdx.x;
    const int warp = tid >> 5;
    const int lane = tid & 31;
    const int g    = lane >> 2;
    const int q    = lane & 3;
    const int sr0  = warp * 16 + g;       // S-phase q rows
    const int sr1  = sr0 + 8;
    const int d0   = (warp & 3) * 16;     // PV d rows
    const int qb   = (warp >> 2) * 64;    // PV q cols

    // ldmatrix lane->address pieces for PV A-frag (V^T via .trans)
    const int lm_kv = ((lane >> 4) & 1) * 8 + (lane & 7);  // kv row within 16-chunk
    const int lm_d  = d0 + ((lane >> 3) & 1) * 8;          // d col (16B slice)

    // load Q tile (scaled by HD^-0.5), fp32 -> half2
    #pragma unroll
    for (int i = 0; i < 8; i++) {
        int idx = tid + i * 256;
        int row = idx >> 4, c4 = (idx & 15) * 4;
        int r = q0 + row;
        float4 v = (r < NN) ? *(const float4*)(Q + baseQ + (long long)r * HD + c4)
                            : make_float4(0.f, 0.f, 0.f, 0.f);
        __half2* p = (__half2*)&Qs[row * HST + c4];
        p[0] = __floats2half2_rn(v.x * 0.125f, v.y * 0.125f);
        p[1] = __floats2half2_rn(v.z * 0.125f, v.w * 0.125f);
    }

    float m0 = -1e30f, m1 = -1e30f, l0 = 0.f, l1 = 0.f;
    float oacc[8][4];
    #pragma unroll
    for (int nt = 0; nt < 8; nt++)
        #pragma unroll
        for (int i = 0; i < 4; i++) oacc[nt][i] = 0.f;

    for (int k0 = 0; k0 < NN; k0 += 64) {
        __syncthreads();
        // load K and V tiles (row-major [kv][d], half)
        #pragma unroll
        for (int i = 0; i < 4; i++) {
            int idx = tid + i * 256;
            int j = idx >> 4, c4 = (idx & 15) * 4;
            int kv = k0 + j;
            float4 kvec, vvec;
            if (kv < NN) {
                kvec = *(const float4*)(K + baseQ + (long long)kv * HD + c4);
                vvec = *(const float4*)(Vy + ((long long)(b * NN + kv)) * DD + h * HD + c4);
            } else {
                kvec = make_float4(0.f, 0.f, 0.f, 0.f);
                vvec = kvec;
            }
            __half2* pk = (__half2*)&Ks[j * HST + c4];
            pk[0] = __floats2half2_rn(kvec.x, kvec.y);
            pk[1] = __floats2half2_rn(kvec.z, kvec.w);
            __half2* pv = (__half2*)&Vs[j * HST + c4];
            pv[0] = __floats2half2_rn(vvec.x, vvec.y);
            pv[1] = __floats2half2_rn(vvec.z, vvec.w);
        }
        __syncthreads();

        // ---- S = Q @ K^T : 16q x 64kv per warp, k-chunks of 16 ----
        float sacc[8][4];
        #pragma unroll
        for (int nt = 0; nt < 8; nt++)
            #pragma unroll
            for (int i = 0; i < 4; i++) sacc[nt][i] = 0.f;

        #pragma unroll
        for (int ks = 0; ks < 4; ks++) {
            const int kc = ks * 16 + 2 * q;
            unsigned a0 = *(const unsigned*)&Qs[sr0 * HST + kc];
            unsigned a1 = *(const unsigned*)&Qs[sr1 * HST + kc];
            unsigned a2 = *(const unsigned*)&Qs[sr0 * HST + kc + 8];
            unsigned a3 = *(const unsigned*)&Qs[sr1 * HST + kc + 8];
            #pragma unroll
            for (int nt = 0; nt < 8; nt++) {
                const __half* kr = &Ks[(nt * 8 + g) * HST + kc];
                unsigned b0 = *(const unsigned*)kr;
                unsigned b1 = *(const unsigned*)(kr + 8);
                mma_f16(sacc[nt][0], sacc[nt][1], sacc[nt][2], sacc[nt][3],
                        a0, a1, a2, a3, b0, b1);
            }
        }

        // mask out-of-range kv
        if (k0 + 64 > NN) {
            #pragma unroll
            for (int nt = 0; nt < 8; nt++) {
                int c = k0 + nt * 8 + 2 * q;
                if (c >= NN)     { sacc[nt][0] = -1e30f; sacc[nt][2] = -1e30f; }
                if (c + 1 >= NN) { sacc[nt][1] = -1e30f; sacc[nt][3] = -1e30f; }
            }
        }

        // online softmax (quad-wide rows)
        float t0 = -1e30f, t1 = -1e30f;
        #pragma unroll
        for (int nt = 0; nt < 8; nt++) {
            t0 = fmaxf(t0, fmaxf(sacc[nt][0], sacc[nt][1]));
            t1 = fmaxf(t1, fmaxf(sacc[nt][2], sacc[nt][3]));
        }
        t0 = fmaxf(t0, __shfl_xor_sync(0xffffffffu, t0, 1));
        t0 = fmaxf(t0, __shfl_xor_sync(0xffffffffu, t0, 2));
        t1 = fmaxf(t1, __shfl_xor_sync(0xffffffffu, t1, 1));
        t1 = fmaxf(t1, __shfl_xor_sync(0xffffffffu, t1, 2));
        float mn0 = fmaxf(m0, t0), mn1 = fmaxf(m1, t1);
        float sc0 = __expf(m0 - mn0), sc1 = __expf(m1 - mn1);
        m0 = mn0; m1 = mn1;

        float ls0 = 0.f, ls1 = 0.f;
        #pragma unroll
        for (int nt = 0; nt < 8; nt++) {
            float p0 = __expf(sacc[nt][0] - mn0);
            float p1 = __expf(sacc[nt][1] - mn0);
            float p2 = __expf(sacc[nt][2] - mn1);
            float p3 = __expf(sacc[nt][3] - mn1);
            ls0 += p0 + p1;
            ls1 += p2 + p3;
            *(__half2*)&Ps[sr0 * HST + nt * 8 + 2 * q] = __floats2half2_rn(p0, p1);
            *(__half2*)&Ps[sr1 * HST + nt * 8 + 2 * q] = __floats2half2_rn(p2, p3);
        }
        ls0 += __shfl_xor_sync(0xffffffffu, ls0, 1);
        ls0 += __shfl_xor_sync(0xffffffffu, ls0, 2);
        ls1 += __shfl_xor_sync(0xffffffffu, ls1, 1);
        ls1 += __shfl_xor_sync(0xffffffffu, ls1, 2);
        l0 = l0 * sc0 + ls0;
        l1 = l1 * sc1 + ls1;
        if (q == 0) { scl[sr0] = sc0; scl[sr1] = sc1; }
        __syncthreads();

        // rescale O accumulators by per-query factor
        #pragma unroll
        for (int nt = 0; nt < 8; nt++) {
            float s0 = scl[qb + nt * 8 + 2 * q];
            float s1 = scl[qb + nt * 8 + 2 * q + 1];
            oacc[nt][0] *= s0; oacc[nt][1] *= s1;
            oacc[nt][2] *= s0; oacc[nt][3] *= s1;
        }
        // ---- PV: O^T += V^T @ P^T, A-frag via ldmatrix.trans ----
        #pragma unroll
        for (int ks = 0; ks < 4; ks++) {
            unsigned a0, a1, a2, a3;
            {
                const __half* src = &Vs[(ks * 16 + lm_kv) * HST + lm_d];
                unsigned saddr = (unsigned)__cvta_generic_to_shared(src);
                asm volatile(
                    "ldmatrix.sync.aligned.m8n8.x4.trans.shared.b16 "
                    "{%0,%1,%2,%3}, [%4];"
                    : "=r"(a0), "=r"(a1), "=r"(a2), "=r"(a3) : "r"(saddr));
            }
            const int kc = ks * 16 + 2 * q;
            #pragma unroll
            for (int nt = 0; nt < 8; nt++) {
                const __half* pr = &Ps[(qb + nt * 8 + g) * HST + kc];
                unsigned b0 = *(const unsigned*)pr;
                unsigned b1 = *(const unsigned*)(pr + 8);
                mma_f16(oacc[nt][0], oacc[nt][1], oacc[nt][2], oacc[nt][3],
                        a0, a1, a2, a3, b0, b1);
            }
        }
    }

    // final 1/l exchange
    if (q == 0) { linv[sr0] = 1.f / l0; linv[sr1] = 1.f / l1; }
    __syncthreads();

    // stage normalized O (transpose back to [query][d]); overlay smem
    float* Osm = (float*)sm_h;   // 128 x OST floats (34816 B < 55296 B)
    #pragma unroll
    for (int nt = 0; nt < 8; nt++) {
        int qc = qb + nt * 8 + 2 * q;
        float i0 = linv[qc], i1 = linv[qc + 1];
        Osm[qc * OST + d0 + g]           = oacc[nt][0] * i0;
        Osm[(qc + 1) * OST + d0 + g]     = oacc[nt][1] * i1;
        Osm[qc * OST + d0 + g + 8]       = oacc[nt][2] * i0;
        Osm[(qc + 1) * OST + d0 + g + 8] = oacc[nt][3] * i1;
    }
    __syncthreads();

    // coalesced output
    #pragma unroll
    for (int i = 0; i < 8; i++) {
        int idx = tid + i * 256;
        int row = idx >> 4, c4 = (idx & 15) * 4;
        int r = q0 + row;
        if (r < NN) {
            float4 v = *(float4*)&Osm[row * OST + c4];
            *(float4*)(CTX + ((long long)(b * NN + r)) * DD + h * HD + c4) = v;
        }
    }
}

// ---------------------------------------------------------------------------
extern "C" void kernel_launch(void* const* d_in, const int* in_sizes, int n_in,
                              void* d_out, int out_size)
{
    const float* X    = (const float*)d_in[0];
    const float* sinp = (const float*)d_in[1];
    const float* cosp = (const float*)d_in[2];
    const float* Wq   = (const float*)d_in[3];
    const float* bq   = (const float*)d_in[4];
    const float* Wk   = (const float*)d_in[5];
    const float* bk   = (const float*)d_in[6];
    const float* Wv   = (const float*)d_in[7];
    const float* bv   = (const float*)d_in[8];
    const float* Wo   = (const float*)d_in[9];
    const float* bo   = (const float*)d_in[10];
    float* OUT = (float*)d_out;

    float *Qb, *Kb, *Vb, *CTX;
    cudaGetSymbolAddress((void**)&Qb,  g_Q);
    cudaGetSymbolAddress((void**)&Kb,  g_K);
    cudaGetSymbolAddress((void**)&Vb,  g_V);
    cudaGetSymbolAddress((void**)&CTX, g_CTX);

    cudaFuncSetAttribute(gemm_tf32<0>,
                         cudaFuncAttributeMaxDynamicSharedMemorySize, GEMM_SMEM);
    cudaFuncSetAttribute(gemm_tf32<1>,
                         cudaFuncAttributeMaxDynamicSharedMemorySize, GEMM_SMEM);
    cudaFuncSetAttribute(flash_attn_tc,
                         cudaFuncAttributeMaxDynamicSharedMemorySize, FA_SMEM);

    dim3 ggrid(DD / 128, (MM + 127) / 128);
    dim3 gblk(256);

    // Q/K projections with fused RoPE+transpose -> [B,H,N,HD]
    gemm_tf32<1><<<ggrid, gblk, GEMM_SMEM>>>(X, Wq, bq, Qb, MM, sinp, cosp);
    gemm_tf32<1><<<ggrid, gblk, GEMM_SMEM>>>(X, Wk, bk, Kb, MM, sinp, cosp);
    // V projection (stays in [B,N,H*HD]; attention reads it directly)
    gemm_tf32<0><<<ggrid, gblk, GEMM_SMEM>>>(X, Wv, bv, Vb, MM, sinp, cosp);

    // fp16 tensor-core attention
    dim3 agrid((NN + 127) / 128, HH, BB);   // (9,16,16)
    flash_attn_tc<<<agrid, 256, FA_SMEM>>>(Qb, Kb, Vb, CTX);

    // output projection straight into d_out
    gemm_tf32<0><<<ggrid, gblk, GEMM_SMEM>>>(CTX, Wo, bo, OUT, MM, sinp, cosp);
}